// round 4
// baseline (speedup 1.0000x reference)
#include <cuda_runtime.h>

#define C_DIM    16
#define DIM_IN   16
#define XPAD     20          // floats per mu1 row in shared (80B stride: 16B-aligned, worst 2-way conflict)
#define MAX_NNZ  1024
#define MAX_ROWS 256
#define MAX_PATHS 64
#define TPB      160         // >= dim3 (156) so each thread owns <=1 output row

__device__ int   g_row_start[MAX_ROWS + 1];
__device__ int   g_row_path[MAX_ROWS];
__device__ int   g_row_order[MAX_ROWS];       // rows sorted by segment length desc
__device__ __align__(16) float g_wT[MAX_PATHS * C_DIM];
__device__ __align__(8)  float2 g_packed[MAX_NNZ];  // {cg, uint((mu1*80)<<4 | mu2)}

// Prep (one tiny block): transpose weights, CSR row starts over sorted mu_3,
// owning path per row, packed static table, and a length-sorted row schedule.
__global__ void tp_prep_kernel(const float* __restrict__ weights,
                               const float* __restrict__ cg,
                               const int* __restrict__ mu1,
                               const int* __restrict__ mu2,
                               const int* __restrict__ mu3,
                               const int* __restrict__ widx,
                               int nnz, int dim3v, int n_paths) {
    int t = threadIdx.x;
    for (int i = t; i < n_paths * C_DIM; i += blockDim.x) {
        int p = i >> 4, c = i & 15;
        g_wT[p * C_DIM + c] = weights[c * n_paths + p];
    }
    for (int m = t; m <= dim3v; m += blockDim.x) {
        int lo = 0, hi = nnz;
        while (lo < hi) {
            int mid = (lo + hi) >> 1;
            if (mu3[mid] < m) lo = mid + 1; else hi = mid;
        }
        g_row_start[m] = lo;
        if (m < dim3v && lo < nnz) g_row_path[m] = widx[lo];
    }
    for (int k = t; k < nnz; k += blockDim.x) {
        unsigned pk = ((unsigned)(mu1[k] * (XPAD * 4)) << 4) | (unsigned)mu2[k];
        g_packed[k] = make_float2(cg[k], __uint_as_float(pk));
    }
    __syncthreads();
    if (t == 0) {
        // insertion sort rows by segment length, descending (structure is
        // identical for all edges, so one schedule serves the whole launch)
        int len[MAX_ROWS];
        for (int m = 0; m < dim3v; ++m) {
            len[m] = g_row_start[m + 1] - g_row_start[m];
            g_row_order[m] = m;
        }
        for (int i = 1; i < dim3v; ++i) {
            int km = g_row_order[i], kl = len[km];
            int j = i - 1;
            while (j >= 0 && len[g_row_order[j]] < kl) {
                g_row_order[j + 1] = g_row_order[j];
                --j;
            }
            g_row_order[j + 1] = km;
        }
    }
}

// One block per edge, 160 threads. Each thread owns one output row (length-
// sorted so warps have uniform trip counts) and accumulates all 16 channels
// in registers: per k -> 1x LDS.64 (cgy + baked x byte-offset) + 4x LDS.128
// (full 64B x row) + 16 FFMA. Epilogue: scale by path weight, 4x STG.128.
__global__ void __launch_bounds__(TPB)
tp_main_kernel(const float* __restrict__ x,
               const float* __restrict__ y,
               float* __restrict__ out,
               int nnz, int dim3v) {
    __shared__ __align__(16) float  x_sh[DIM_IN * XPAD];
    __shared__ __align__(8)  float2 ent_sh[MAX_NNZ];

    const int e = blockIdx.x;
    const int t = threadIdx.x;

    // stage x[e] : x[e][row][c] -> x_sh[row*XPAD + c]
    for (int i = t; i < DIM_IN * C_DIM; i += TPB) {
        x_sh[(i >> 4) * XPAD + (i & 15)] = x[e * (DIM_IN * C_DIM) + i];
    }
    // build per-edge table: ent[k] = { cg[k]*y[e,mu2[k]], x byte-offset }
    const float* ye = y + e * DIM_IN;
    for (int k = t; k < nnz; k += TPB) {
        float2 p = g_packed[k];
        unsigned pk = __float_as_uint(p.y);
        float cgy = p.x * __ldg(&ye[pk & 15u]);
        ent_sh[k] = make_float2(cgy, __uint_as_float(pk >> 4));
    }
    __syncthreads();

    float* outE = out + (size_t)e * dim3v * C_DIM;

    for (int i = t; i < dim3v; i += TPB) {
        const int m3 = g_row_order[i];
        const int s  = g_row_start[m3];
        const int en = g_row_start[m3 + 1];
        float acc[16];
        #pragma unroll
        for (int c = 0; c < 16; ++c) acc[c] = 0.f;

        for (int k = s; k < en; ++k) {
            float2 ent = ent_sh[k];
            const float4* xr = (const float4*)((const char*)x_sh + __float_as_int(ent.y));
            #pragma unroll
            for (int q = 0; q < 4; ++q) {
                float4 xv = xr[q];
                acc[4*q + 0] = fmaf(xv.x, ent.x, acc[4*q + 0]);
                acc[4*q + 1] = fmaf(xv.y, ent.x, acc[4*q + 1]);
                acc[4*q + 2] = fmaf(xv.z, ent.x, acc[4*q + 2]);
                acc[4*q + 3] = fmaf(xv.w, ent.x, acc[4*q + 3]);
            }
        }

        const float* wrow = g_wT + g_row_path[m3] * C_DIM;
        float* dst = outE + m3 * C_DIM;
        #pragma unroll
        for (int q = 0; q < 4; ++q) {
            float4 wv = *(const float4*)(wrow + 4*q);
            float4 o;
            o.x = acc[4*q + 0] * wv.x;
            o.y = acc[4*q + 1] * wv.y;
            o.z = acc[4*q + 2] * wv.z;
            o.w = acc[4*q + 3] * wv.w;
            *(float4*)(dst + 4*q) = o;
        }
    }
}

extern "C" void kernel_launch(void* const* d_in, const int* in_sizes, int n_in,
                              void* d_out, int out_size) {
    const float* x      = (const float*)d_in[0];
    const float* y      = (const float*)d_in[1];
    const float* cg     = (const float*)d_in[2];
    const float* w      = (const float*)d_in[3];
    const int*   mu1    = (const int*)d_in[4];
    const int*   mu2    = (const int*)d_in[5];
    const int*   mu3    = (const int*)d_in[6];
    const int*   widx   = (const int*)d_in[7];

    const int nnz     = in_sizes[4];
    const int E       = in_sizes[1] / DIM_IN;
    const int dim3v   = out_size / (E * C_DIM);
    const int n_paths = in_sizes[3] / C_DIM;

    tp_prep_kernel<<<1, 256>>>(w, cg, mu1, mu2, mu3, widx, nnz, dim3v, n_paths);
    tp_main_kernel<<<E, TPB>>>(x, y, (float*)d_out, nnz, dim3v);
}

// round 5
// speedup vs baseline: 6.2624x; 6.2624x over previous
#include <cuda_runtime.h>

#define C_DIM    16
#define DIM_IN   16
#define XPAD     20          // floats per mu1 row in shared (80B stride: 16B-aligned)
#define MAX_NNZ  1024
#define MAX_ROWS 256
#define MAX_PATHS 64

__device__ int   g_row_start[MAX_ROWS + 1];
__device__ int   g_row_path[MAX_ROWS];
__device__ int   g_row_order[MAX_ROWS];       // rows sorted by segment length desc
__device__ __align__(16) float  g_wT[MAX_PATHS * C_DIM];
__device__ __align__(8)  float2 g_packed[MAX_NNZ];  // {cg, uint((mu1*80)<<4 | mu2)}

// Prep (one block, 256 threads, all parallel — NO serial sort):
//  - transpose weights to [path][c]
//  - CSR row starts over globally-sorted mu_3 (binary search per row)
//  - owning path per row; packed static table {cg, mu1-byteoff | mu2}
//  - length-descending row schedule via parallel rank-by-count
__global__ void tp_prep_kernel(const float* __restrict__ weights,
                               const float* __restrict__ cg,
                               const int* __restrict__ mu1,
                               const int* __restrict__ mu2,
                               const int* __restrict__ mu3,
                               const int* __restrict__ widx,
                               int nnz, int dim3v, int n_paths) {
    __shared__ int len_sh[MAX_ROWS];
    const int t = threadIdx.x;

    for (int i = t; i < n_paths * C_DIM; i += blockDim.x) {
        int p = i >> 4, c = i & 15;
        g_wT[p * C_DIM + c] = weights[c * n_paths + p];
    }
    for (int m = t; m <= dim3v; m += blockDim.x) {
        int lo = 0, hi = nnz;
        while (lo < hi) {
            int mid = (lo + hi) >> 1;
            if (mu3[mid] < m) lo = mid + 1; else hi = mid;
        }
        g_row_start[m] = lo;
        if (m < dim3v && lo < nnz) g_row_path[m] = widx[lo];
    }
    for (int k = t; k < nnz; k += blockDim.x) {
        unsigned pk = ((unsigned)(mu1[k] * (XPAD * 4)) << 4) | (unsigned)mu2[k];
        g_packed[k] = make_float2(cg[k], __uint_as_float(pk));
    }
    __syncthreads();

    // segment lengths into shared
    for (int m = t; m < dim3v; m += blockDim.x)
        len_sh[m] = g_row_start[m + 1] - g_row_start[m];
    __syncthreads();

    // rank = #rows strictly longer, ties broken by index -> stable desc order
    for (int m = t; m < dim3v; m += blockDim.x) {
        const int lm = len_sh[m];
        int rank = 0;
        for (int o = 0; o < dim3v; ++o) {
            int lo_ = len_sh[o];
            rank += (lo_ > lm) || (lo_ == lm && o < m);
        }
        g_row_order[rank] = m;
    }
}

// One block per edge, 256 threads: q = tid&3 -> channel quad, r = tid>>2 -> slot.
// Slots walk the length-sorted row order so all lanes in a warp run near-equal
// trip counts. Per k: LDS.64 ent (broadcast across the 4 quads) + LDS.128 x
// slice + 4 FFMA. Epilogue: scale by owning path weight, STG.128.
__global__ void __launch_bounds__(256)
tp_main_kernel(const float* __restrict__ x,
               const float* __restrict__ y,
               float* __restrict__ out,
               int nnz, int dim3v) {
    __shared__ __align__(16) float  x_sh[DIM_IN * XPAD];
    __shared__ __align__(8)  float2 ent_sh[MAX_NNZ];

    const int e = blockIdx.x;
    const int t = threadIdx.x;

    // stage x[e] : x[e][row][c] -> x_sh[row*XPAD + c]
    {
        float v = x[e * (DIM_IN * C_DIM) + t];
        x_sh[(t >> 4) * XPAD + (t & 15)] = v;
    }
    // per-edge table: ent[k] = { cg[k]*y[e,mu2[k]], x byte-offset }
    const float* ye = y + e * DIM_IN;
    for (int k = t; k < nnz; k += 256) {
        float2 p = g_packed[k];
        unsigned pk = __float_as_uint(p.y);
        float cgy = p.x * __ldg(&ye[pk & 15u]);
        ent_sh[k] = make_float2(cgy, __uint_as_float(pk >> 4));
    }
    __syncthreads();

    const int q = t & 3;          // channel quad
    const int r = t >> 2;         // schedule slot 0..63
    const char* xb = (const char*)x_sh + q * 16;
    float* outE = out + (size_t)e * dim3v * C_DIM;

    for (int i = r; i < dim3v; i += 64) {
        const int m3 = g_row_order[i];
        const int s  = g_row_start[m3];
        const int en = g_row_start[m3 + 1];
        float4 acc = make_float4(0.f, 0.f, 0.f, 0.f);
        #pragma unroll 2
        for (int k = s; k < en; ++k) {
            float2 ent = ent_sh[k];
            const float4 xv = *(const float4*)(xb + __float_as_int(ent.y));
            acc.x = fmaf(xv.x, ent.x, acc.x);
            acc.y = fmaf(xv.y, ent.x, acc.y);
            acc.z = fmaf(xv.z, ent.x, acc.z);
            acc.w = fmaf(xv.w, ent.x, acc.w);
        }
        const float4 wv = *(const float4*)(g_wT + g_row_path[m3] * C_DIM + q * 4);
        acc.x *= wv.x; acc.y *= wv.y; acc.z *= wv.z; acc.w *= wv.w;
        *(float4*)(outE + m3 * C_DIM + q * 4) = acc;
    }
}

extern "C" void kernel_launch(void* const* d_in, const int* in_sizes, int n_in,
                              void* d_out, int out_size) {
    const float* x      = (const float*)d_in[0];
    const float* y      = (const float*)d_in[1];
    const float* cg     = (const float*)d_in[2];
    const float* w      = (const float*)d_in[3];
    const int*   mu1    = (const int*)d_in[4];
    const int*   mu2    = (const int*)d_in[5];
    const int*   mu3    = (const int*)d_in[6];
    const int*   widx   = (const int*)d_in[7];

    const int nnz     = in_sizes[4];
    const int E       = in_sizes[1] / DIM_IN;
    const int dim3v   = out_size / (E * C_DIM);
    const int n_paths = in_sizes[3] / C_DIM;

    tp_prep_kernel<<<1, 256>>>(w, cg, mu1, mu2, mu3, widx, nnz, dim3v, n_paths);
    tp_main_kernel<<<E, 256>>>(x, y, (float*)d_out, nnz, dim3v);
}